// round 11
// baseline (speedup 1.0000x reference)
#include <cuda_runtime.h>
#include <cuda_bf16.h>

// Problem constants
#define B_   128
#define F_   80
#define T_   4000
#define FREQ_MASKS 2
#define TIME_MASKS 10
#define FSPAN 28u    // MAX_FREQ - MIN_FREQ + 1
#define TSPAN 101u   // MAX_TIME - MIN_TIME + 1

// ---------------------------------------------------------------------------
// Threefry-2x32, 20 rounds (JAX rotation schedule)
// ---------------------------------------------------------------------------
__device__ __forceinline__ void tf2x32(unsigned k0, unsigned k1,
                                       unsigned x0, unsigned x1,
                                       unsigned& o0, unsigned& o1) {
    const unsigned ks2 = k0 ^ k1 ^ 0x1BD11BDAu;
#define TF_ROUND(r) do { x0 += x1; x1 = __funnelshift_l(x1, x1, (r)); x1 ^= x0; } while (0)
    x0 += k0;  x1 += k1;
    TF_ROUND(13); TF_ROUND(15); TF_ROUND(26); TF_ROUND(6);
    x0 += k1;  x1 += ks2 + 1u;
    TF_ROUND(17); TF_ROUND(29); TF_ROUND(16); TF_ROUND(24);
    x0 += ks2; x1 += k0 + 2u;
    TF_ROUND(13); TF_ROUND(15); TF_ROUND(26); TF_ROUND(6);
    x0 += k0;  x1 += k1 + 3u;
    TF_ROUND(17); TF_ROUND(29); TF_ROUND(16); TF_ROUND(24);
    x0 += k1;  x1 += ks2 + 4u;
    TF_ROUND(13); TF_ROUND(15); TF_ROUND(26); TF_ROUND(6);
    x0 += ks2; x1 += k0 + 5u;
#undef TF_ROUND
    o0 = x0; o1 = x1;
}

// partitionable-mode random_bits: flat index i -> y0 ^ y1 of counter (0, i)
__device__ __forceinline__ unsigned xorbits(unsigned k0, unsigned k1, unsigned idx) {
    unsigned a, b;
    tf2x32(k0, k1, 0u, idx, a, b);
    return a ^ b;
}

// ---------------------------------------------------------------------------
// Fused kernel. grid = B_*F_ blocks (one per (b,f) row), 256 threads.
// Phase 1: threads 0..11 derive the 12 mask intervals for batch b.
// Phase 2: threads 0..124 expand time-mask bits into shared memory;
//          thread 0 evaluates the freq mask for this row's f.
// Phase 3: stream the 4000-float row (float4), zeroing masked positions.
// Freq-masked rows write zeros without reading x.
// ---------------------------------------------------------------------------
__global__ void __launch_bounds__(256) specaug_kernel(const float4* __restrict__ x,
                                                      float4* __restrict__ out) {
    const int bf  = blockIdx.x;           // b * F_ + f
    const int b   = bf / F_;
    const int f   = bf - b * F_;
    const int tid = threadIdx.x;

    __shared__ int      s_start[12];
    __shared__ int      s_end[12];
    __shared__ unsigned s_tbits[T_ / 32]; // 125 words
    __shared__ int      s_fm;

    if (tid < 12) {
        // key(42) = (0, 42); foldlike split: child i = tf(key, (0, i))
        unsigned kf0, kf1, kt0, kt1;
        tf2x32(0u, 42u, 0u, 0u, kf0, kf1);   // kf
        tf2x32(0u, 42u, 0u, 1u, kt0, kt1);   // kt

        unsigned k0, k1, span;
        int dim, M;
        if (tid < 2) { k0 = kf0; k1 = kf1; dim = F_; M = FREQ_MASKS; span = FSPAN; }
        else         { k0 = kt0; k1 = kt1; dim = T_; M = TIME_MASKS; span = TSPAN; }

        // kw, ks = split(band key)  (foldlike)
        unsigned kw0, kw1, ks0, ks1;
        tf2x32(k0, k1, 0u, 0u, kw0, kw1);
        tf2x32(k0, k1, 0u, 1u, ks0, ks1);

        const int m = (tid < 2) ? tid : (tid - 2);
        const unsigned idx = (unsigned)(b * M + m);

        // JAX _randint internally re-splits its key:
        //   k1, k2 = split(kw); higher = random_bits(k1, 32, shape)[idx];
        //                       lower  = random_bits(k2, 32, shape)[idx]
        unsigned kr10, kr11, kr20, kr21;
        tf2x32(kw0, kw1, 0u, 0u, kr10, kr11);   // k1
        tf2x32(kw0, kw1, 0u, 1u, kr20, kr21);   // k2
        const unsigned hib = xorbits(kr10, kr11, idx);
        const unsigned lob = xorbits(kr20, kr21, idx);

        unsigned mult = 65536u % span;
        mult = (mult * mult) % span;
        const unsigned w = ((hib % span) * mult + (lob % span)) % span;

        // uniform(ks, (B, M)) element idx (direct draw, no internal split)
        const unsigned ub = xorbits(ks0, ks1, idx);
        const float u = __uint_as_float((ub >> 9) | 0x3f800000u) - 1.0f;

        int hirange = dim - (int)w;
        if (hirange < 1) hirange = 1;
        const int start = (int)floorf(u * (float)hirange);

        s_start[tid] = start;
        s_end[tid]   = start + (int)w;
    }
    __syncthreads();

    if (tid == 0) {
        s_fm = ((f >= s_start[0] && f < s_end[0]) ||
                (f >= s_start[1] && f < s_end[1])) ? 1 : 0;
    }
    if (tid < (T_ / 32)) {   // 125 words
        const int w0 = tid * 32;
        unsigned bits = 0u;
#pragma unroll
        for (int m = 0; m < TIME_MASKS; m++) {
            int lo = s_start[2 + m]; if (lo < w0)      lo = w0;
            int hi = s_end[2 + m];   if (hi > w0 + 32) hi = w0 + 32;
            if (hi > lo) {
                const int n = hi - lo;
                const unsigned msk = (n >= 32) ? 0xFFFFFFFFu
                                               : (((1u << n) - 1u) << (lo - w0));
                bits |= msk;
            }
        }
        s_tbits[tid] = bits;
    }
    __syncthreads();

    const int rowbase = bf * (T_ / 4);   // 1000 float4 per row

    if (s_fm) {
        const float4 z = make_float4(0.f, 0.f, 0.f, 0.f);
#pragma unroll
        for (int k = 0; k < 4; k++) {
            const int idx = tid + k * 256;
            if (idx < T_ / 4) out[rowbase + idx] = z;
        }
        return;
    }

#pragma unroll
    for (int k = 0; k < 4; k++) {
        const int idx = tid + k * 256;
        if (idx < T_ / 4) {
            const int t0 = idx * 4;
            const unsigned nib = (s_tbits[t0 >> 5] >> (t0 & 31)) & 0xFu;
            float4 v = x[rowbase + idx];
            if (nib & 1u) v.x = 0.f;
            if (nib & 2u) v.y = 0.f;
            if (nib & 4u) v.z = 0.f;
            if (nib & 8u) v.w = 0.f;
            out[rowbase + idx] = v;
        }
    }
}

// ---------------------------------------------------------------------------
extern "C" void kernel_launch(void* const* d_in, const int* in_sizes, int n_in,
                              void* d_out, int out_size) {
    (void)in_sizes; (void)n_in; (void)out_size;
    const float4* x = (const float4*)d_in[0];
    float4* out     = (float4*)d_out;

    specaug_kernel<<<B_ * F_, 256>>>(x, out);
}

// round 16
// speedup vs baseline: 1.0114x; 1.0114x over previous
#include <cuda_runtime.h>
#include <cuda_bf16.h>

// Problem constants
#define B_   128
#define F_   80
#define T_   4000
#define FREQ_MASKS 2
#define TIME_MASKS 10
#define FSPAN 28u    // MAX_FREQ - MIN_FREQ + 1
#define TSPAN 101u   // MAX_TIME - MIN_TIME + 1

#define TWORDS 128   // 125 words used per batch, padded stride

// Persistent scratch (allocation-free)
__device__ unsigned int  g_tbits[B_ * TWORDS];
__device__ unsigned char g_fmask[B_ * F_];

// ---------------------------------------------------------------------------
// Threefry-2x32, 20 rounds (JAX rotation schedule)
// ---------------------------------------------------------------------------
__device__ __forceinline__ void tf2x32(unsigned k0, unsigned k1,
                                       unsigned x0, unsigned x1,
                                       unsigned& o0, unsigned& o1) {
    const unsigned ks2 = k0 ^ k1 ^ 0x1BD11BDAu;
#define TF_ROUND(r) do { x0 += x1; x1 = __funnelshift_l(x1, x1, (r)); x1 ^= x0; } while (0)
    x0 += k0;  x1 += k1;
    TF_ROUND(13); TF_ROUND(15); TF_ROUND(26); TF_ROUND(6);
    x0 += k1;  x1 += ks2 + 1u;
    TF_ROUND(17); TF_ROUND(29); TF_ROUND(16); TF_ROUND(24);
    x0 += ks2; x1 += k0 + 2u;
    TF_ROUND(13); TF_ROUND(15); TF_ROUND(26); TF_ROUND(6);
    x0 += k0;  x1 += k1 + 3u;
    TF_ROUND(17); TF_ROUND(29); TF_ROUND(16); TF_ROUND(24);
    x0 += k1;  x1 += ks2 + 4u;
    TF_ROUND(13); TF_ROUND(15); TF_ROUND(26); TF_ROUND(6);
    x0 += ks2; x1 += k0 + 5u;
#undef TF_ROUND
    o0 = x0; o1 = x1;
}

// partitionable-mode random_bits: flat index i -> y0 ^ y1 of counter (0, i)
__device__ __forceinline__ unsigned xorbits(unsigned k0, unsigned k1, unsigned idx) {
    unsigned a, b;
    tf2x32(k0, k1, 0u, idx, a, b);
    return a ^ b;
}

// ---------------------------------------------------------------------------
// Kernel 1: build masks once. grid = B_ blocks, 128 threads.
// ---------------------------------------------------------------------------
__global__ void build_masks_kernel() {
    const int b   = blockIdx.x;
    const int tid = threadIdx.x;

    __shared__ int s_start[12];
    __shared__ int s_end[12];

    if (tid < 12) {
        // key(42) = (0, 42); foldlike split: child i = tf(key, (0, i))
        unsigned kf0, kf1, kt0, kt1;
        tf2x32(0u, 42u, 0u, 0u, kf0, kf1);   // kf
        tf2x32(0u, 42u, 0u, 1u, kt0, kt1);   // kt

        unsigned k0, k1, span;
        int dim, M;
        if (tid < 2) { k0 = kf0; k1 = kf1; dim = F_; M = FREQ_MASKS; span = FSPAN; }
        else         { k0 = kt0; k1 = kt1; dim = T_; M = TIME_MASKS; span = TSPAN; }

        // kw, ks = split(band key)  (foldlike)
        unsigned kw0, kw1, ks0, ks1;
        tf2x32(k0, k1, 0u, 0u, kw0, kw1);
        tf2x32(k0, k1, 0u, 1u, ks0, ks1);

        const int m = (tid < 2) ? tid : (tid - 2);
        const unsigned idx = (unsigned)(b * M + m);

        // JAX _randint internally re-splits: k1, k2 = split(kw);
        // higher = bits(k1)[idx]; lower = bits(k2)[idx]
        unsigned kr10, kr11, kr20, kr21;
        tf2x32(kw0, kw1, 0u, 0u, kr10, kr11);
        tf2x32(kw0, kw1, 0u, 1u, kr20, kr21);
        const unsigned hib = xorbits(kr10, kr11, idx);
        const unsigned lob = xorbits(kr20, kr21, idx);

        unsigned mult = 65536u % span;
        mult = (mult * mult) % span;
        const unsigned w = ((hib % span) * mult + (lob % span)) % span;

        // uniform(ks, (B, M)) element idx
        const unsigned ub = xorbits(ks0, ks1, idx);
        const float u = __uint_as_float((ub >> 9) | 0x3f800000u) - 1.0f;

        int hirange = dim - (int)w;
        if (hirange < 1) hirange = 1;
        const int start = (int)floorf(u * (float)hirange);

        s_start[tid] = start;
        s_end[tid]   = start + (int)w;
    }
    __syncthreads();

    if (tid < F_) {
        const bool fm = (tid >= s_start[0] && tid < s_end[0]) ||
                        (tid >= s_start[1] && tid < s_end[1]);
        g_fmask[b * F_ + tid] = fm ? 1u : 0u;
    }

    if (tid < (T_ / 32)) {   // 125 words
        const int w0 = tid * 32;
        unsigned bits = 0u;
#pragma unroll
        for (int m = 0; m < TIME_MASKS; m++) {
            int lo = s_start[2 + m]; if (lo < w0)      lo = w0;
            int hi = s_end[2 + m];   if (hi > w0 + 32) hi = w0 + 32;
            if (hi > lo) {
                const int n = hi - lo;
                const unsigned msk = (n >= 32) ? 0xFFFFFFFFu
                                               : (((1u << n) - 1u) << (lo - w0));
                bits |= msk;
            }
        }
        g_tbits[b * TWORDS + tid] = bits;
    }
}

// ---------------------------------------------------------------------------
// Kernel 2: pure streaming apply. grid = B_*F_ rows, 256 threads, float4.
// No RNG, no shared memory, no barriers. Front-batched loads for MLP.
// Freq-masked rows write zeros without reading x.
// ---------------------------------------------------------------------------
__global__ void __launch_bounds__(256) apply_kernel(const float4* __restrict__ x,
                                                    float4* __restrict__ out) {
    const int bf  = blockIdx.x;            // b * F_ + f
    const int b   = bf / F_;
    const int tid = threadIdx.x;
    const int rowbase = bf * (T_ / 4);     // 1000 float4 per row

    if (g_fmask[bf]) {
        const float4 z = make_float4(0.f, 0.f, 0.f, 0.f);
#pragma unroll
        for (int k = 0; k < 4; k++) {
            const int idx = tid + k * 256;
            if (idx < T_ / 4) __stcs(&out[rowbase + idx], z);
        }
        return;
    }

    const unsigned* __restrict__ tb = &g_tbits[b * TWORDS];

    // Front-batch all loads (independent) for maximum MLP, then combine.
    unsigned nib[4];
    float4   v[4];
#pragma unroll
    for (int k = 0; k < 4; k++) {
        const int idx = tid + k * 256;
        if (idx < T_ / 4) {
            const int t0 = idx * 4;
            nib[k] = (__ldg(&tb[t0 >> 5]) >> (t0 & 31)) & 0xFu;
            v[k]   = __ldcs(&x[rowbase + idx]);
        }
    }
#pragma unroll
    for (int k = 0; k < 4; k++) {
        const int idx = tid + k * 256;
        if (idx < T_ / 4) {
            float4 r = v[k];
            if (nib[k] & 1u) r.x = 0.f;
            if (nib[k] & 2u) r.y = 0.f;
            if (nib[k] & 4u) r.z = 0.f;
            if (nib[k] & 8u) r.w = 0.f;
            __stcs(&out[rowbase + idx], r);
        }
    }
}

// ---------------------------------------------------------------------------
extern "C" void kernel_launch(void* const* d_in, const int* in_sizes, int n_in,
                              void* d_out, int out_size) {
    (void)in_sizes; (void)n_in; (void)out_size;
    const float4* x = (const float4*)d_in[0];
    float4* out     = (float4*)d_out;

    build_masks_kernel<<<B_, 128>>>();
    apply_kernel<<<B_ * F_, 256>>>(x, out);
}